// round 1
// baseline (speedup 1.0000x reference)
#include <cuda_runtime.h>
#include <cuda_bf16.h>
#include <math.h>

// ---------------------------------------------------------------------------
// MessageBlock:
//   phi_node = Linear2(silu(Linear1(s)))           (per-NODE, not per-edge!)
//   per edge e: W = (rbf @ Wrbf^T + brbf) * fcut(d)
//               msg = phi_node[src] * W  -> split ws/wvv/wvs
//               ds[dst]   += ws
//               dvec[dst] += wvv*vec[src] + (ev/d) outer wvs
// ---------------------------------------------------------------------------

#define F_DIM   128
#define PHI_DIM 384
#define RBF_D   20
#define TILE_M  32
#define KC      16
#define EB      64   // edges staged per batch

// scratch for per-node phi (15.7 MB), static device allocation (allowed)
__device__ float g_phi[10240 * PHI_DIM];

__device__ __forceinline__ float decode_rc(const int* p) {
    int v = *p;
    if (v > 0 && v < 1000000) return (float)v;   // int32 scalar
    return __uint_as_float((unsigned)v);          // float32 scalar bits
}

// ---------------------------------------------------------------------------
// zero-fill output
// ---------------------------------------------------------------------------
__global__ void zero_kernel(float* __restrict__ p, int n) {
    int i = (blockIdx.x * blockDim.x + threadIdx.x) * 4;
    if (i + 3 < n) {
        *(float4*)(p + i) = make_float4(0.f, 0.f, 0.f, 0.f);
    } else {
        for (int k = i; k < n; k++) p[k] = 0.f;
    }
}

// ---------------------------------------------------------------------------
// Node MLP: phi = (silu(s @ Ws1^T + bs1)) @ Ws2^T + bs2   -> g_phi [N,384]
// Block: 256 threads, TILE_M=32 nodes. Register tile 4x4, k-chunks of 16 in smem.
// ---------------------------------------------------------------------------
__global__ void __launch_bounds__(256) node_mlp_kernel(
    const float* __restrict__ s,
    const float* __restrict__ Ws1, const float* __restrict__ bs1,
    const float* __restrict__ Ws2, const float* __restrict__ bs2,
    int n_nodes)
{
    __shared__ float s_sm[TILE_M][F_DIM];     // 16 KB
    __shared__ float h_sm[TILE_M][F_DIM];     // 16 KB
    __shared__ float w_sm[KC][F_DIM + 4];     // ~8.25 KB, [k][n], pad keeps 16B align

    const int tid   = threadIdx.x;
    const int m_blk = blockIdx.x * TILE_M;
    const int n_idx = tid & 31;       // 32 n-groups of 4  -> n in [0,128)
    const int m_idx = tid >> 5;       // 8  m-groups of 4  -> m in [0,32)
    const int n0 = n_idx * 4;
    const int m0 = m_idx * 4;

    // stage s tile (zero-pad past n_nodes)
    for (int i = tid; i < TILE_M * 32; i += 256) {
        int m = i >> 5;
        float4 v = make_float4(0.f, 0.f, 0.f, 0.f);
        if (m_blk + m < n_nodes)
            v = ((const float4*)s)[(size_t)(m_blk + m) * 32 + (i & 31)];
        ((float4*)s_sm)[i] = v;
    }

    float acc[4][4];

    // ---------------- stage 1: h = silu(s @ Ws1^T + bs1) ----------------
    #pragma unroll
    for (int i = 0; i < 4; i++)
        #pragma unroll
        for (int j = 0; j < 4; j++) acc[i][j] = 0.f;

    for (int kc = 0; kc < F_DIM; kc += KC) {
        __syncthreads();
        for (int i = tid; i < KC * F_DIM; i += 256) {
            int kk = i & (KC - 1);
            int n  = i >> 4;
            w_sm[kk][n] = Ws1[n * F_DIM + kc + kk];
        }
        __syncthreads();
        #pragma unroll
        for (int k4 = 0; k4 < KC; k4 += 4) {
            float a[4][4];
            #pragma unroll
            for (int i = 0; i < 4; i++) {
                float4 t = *(const float4*)&s_sm[m0 + i][kc + k4];
                a[i][0] = t.x; a[i][1] = t.y; a[i][2] = t.z; a[i][3] = t.w;
            }
            #pragma unroll
            for (int kk = 0; kk < 4; kk++) {
                float4 b = *(const float4*)&w_sm[k4 + kk][n0];
                #pragma unroll
                for (int i = 0; i < 4; i++) {
                    acc[i][0] = fmaf(a[i][kk], b.x, acc[i][0]);
                    acc[i][1] = fmaf(a[i][kk], b.y, acc[i][1]);
                    acc[i][2] = fmaf(a[i][kk], b.z, acc[i][2]);
                    acc[i][3] = fmaf(a[i][kk], b.w, acc[i][3]);
                }
            }
        }
    }
    // silu + bias -> h_sm
    {
        float bb[4];
        #pragma unroll
        for (int j = 0; j < 4; j++) bb[j] = bs1[n0 + j];
        #pragma unroll
        for (int i = 0; i < 4; i++) {
            float4 hv;
            float x;
            x = acc[i][0] + bb[0]; hv.x = x / (1.f + __expf(-x));
            x = acc[i][1] + bb[1]; hv.y = x / (1.f + __expf(-x));
            x = acc[i][2] + bb[2]; hv.z = x / (1.f + __expf(-x));
            x = acc[i][3] + bb[3]; hv.w = x / (1.f + __expf(-x));
            *(float4*)&h_sm[m0 + i][n0] = hv;
        }
    }

    // ---------------- stage 2: phi = h @ Ws2^T + bs2 (3 passes of 128) --
    for (int p = 0; p < 3; p++) {
        #pragma unroll
        for (int i = 0; i < 4; i++)
            #pragma unroll
            for (int j = 0; j < 4; j++) acc[i][j] = 0.f;

        const float* W2 = Ws2 + (size_t)p * 128 * F_DIM;
        for (int kc = 0; kc < F_DIM; kc += KC) {
            __syncthreads();   // also orders h_sm writes before first read
            for (int i = tid; i < KC * F_DIM; i += 256) {
                int kk = i & (KC - 1);
                int n  = i >> 4;
                w_sm[kk][n] = W2[n * F_DIM + kc + kk];
            }
            __syncthreads();
            #pragma unroll
            for (int k4 = 0; k4 < KC; k4 += 4) {
                float a[4][4];
                #pragma unroll
                for (int i = 0; i < 4; i++) {
                    float4 t = *(const float4*)&h_sm[m0 + i][kc + k4];
                    a[i][0] = t.x; a[i][1] = t.y; a[i][2] = t.z; a[i][3] = t.w;
                }
                #pragma unroll
                for (int kk = 0; kk < 4; kk++) {
                    float4 b = *(const float4*)&w_sm[k4 + kk][n0];
                    #pragma unroll
                    for (int i = 0; i < 4; i++) {
                        acc[i][0] = fmaf(a[i][kk], b.x, acc[i][0]);
                        acc[i][1] = fmaf(a[i][kk], b.y, acc[i][1]);
                        acc[i][2] = fmaf(a[i][kk], b.z, acc[i][2]);
                        acc[i][3] = fmaf(a[i][kk], b.w, acc[i][3]);
                    }
                }
            }
        }
        float bb[4];
        #pragma unroll
        for (int j = 0; j < 4; j++) bb[j] = bs2[p * 128 + n0 + j];
        #pragma unroll
        for (int i = 0; i < 4; i++) {
            if (m_blk + m0 + i < n_nodes) {
                float4 ov = make_float4(acc[i][0] + bb[0], acc[i][1] + bb[1],
                                        acc[i][2] + bb[2], acc[i][3] + bb[3]);
                *(float4*)&g_phi[(size_t)(m_blk + m0 + i) * PHI_DIM + p * 128 + n0] = ov;
            }
        }
    }
}

// ---------------------------------------------------------------------------
// Edge kernel: 128 threads, thread t owns feature channels {t, t+128, t+256}.
// Wrbf rows for those channels live in registers (60 regs). Edges staged in
// batches of EB into smem; rbf values broadcast from smem; scatter via RED.
// ---------------------------------------------------------------------------
__global__ void __launch_bounds__(128) edge_kernel(
    const float* __restrict__ vec,
    const float* __restrict__ edge_vector,
    const float* __restrict__ edge_distance,
    const float* __restrict__ edge_rbf,
    const float* __restrict__ Wrbf, const float* __restrict__ brbf,
    const int*   __restrict__ edge_idx,
    float* __restrict__ out_ds, float* __restrict__ out_dvec,
    int n_edges, const int* __restrict__ cutoff_ptr)
{
    __shared__ float rbf_sm[EB * RBF_D];
    __shared__ int   src_sm[EB];
    __shared__ int   dst_sm[EB];
    __shared__ float fcut_sm[EB];
    __shared__ float vn_sm[EB][3];

    const int tid = threadIdx.x;
    const float rc     = decode_rc(cutoff_ptr);
    const float inv_rc = 1.0f / rc;

    float w0[RBF_D], w1[RBF_D], w2[RBF_D];
    #pragma unroll
    for (int r = 0; r < RBF_D; r++) {
        w0[r] = Wrbf[(tid       ) * RBF_D + r];
        w1[r] = Wrbf[(tid + 128 ) * RBF_D + r];
        w2[r] = Wrbf[(tid + 256 ) * RBF_D + r];
    }
    const float b0 = brbf[tid], b1 = brbf[tid + 128], b2 = brbf[tid + 256];

    const int n_batches = (n_edges + EB - 1) / EB;
    for (int batch = blockIdx.x; batch < n_batches; batch += gridDim.x) {
        const int e0  = batch * EB;
        const int cnt = min(EB, n_edges - e0);

        __syncthreads();  // protect smem reuse across batches
        for (int i = tid; i < cnt * RBF_D; i += 128)
            rbf_sm[i] = edge_rbf[(size_t)e0 * RBF_D + i];
        if (tid < cnt) {
            const int e = e0 + tid;
            const float d = edge_distance[e];
            float fc = 0.5f * (cospif(d * inv_rc) + 1.0f);
            fcut_sm[tid] = (d < rc) ? fc : 0.0f;
            const float inv_d = 1.0f / d;
            vn_sm[tid][0] = edge_vector[e * 3 + 0] * inv_d;
            vn_sm[tid][1] = edge_vector[e * 3 + 1] * inv_d;
            vn_sm[tid][2] = edge_vector[e * 3 + 2] * inv_d;
            dst_sm[tid] = edge_idx[e];             // row 0: receivers
            src_sm[tid] = edge_idx[n_edges + e];   // row 1: senders
        }
        __syncthreads();

        for (int el = 0; el < cnt; el++) {
            const int src = src_sm[el];
            const int dst = dst_sm[el];
            const float fc = fcut_sm[el];

            float a0 = b0, a1 = b1, a2 = b2;
            #pragma unroll
            for (int r = 0; r < RBF_D; r++) {
                const float f = rbf_sm[el * RBF_D + r];
                a0 = fmaf(f, w0[r], a0);
                a1 = fmaf(f, w1[r], a1);
                a2 = fmaf(f, w2[r], a2);
            }

            const float* ph = g_phi + (size_t)src * PHI_DIM;
            const float ws  = ph[tid]       * a0 * fc;
            const float wvv = ph[tid + 128] * a1 * fc;
            const float wvs = ph[tid + 256] * a2 * fc;

            atomicAdd(out_ds + (size_t)dst * F_DIM + tid, ws);

            const float* vp = vec + (size_t)src * PHI_DIM;
            float* op = out_dvec + (size_t)dst * PHI_DIM + tid;
            const float vn0 = vn_sm[el][0], vn1 = vn_sm[el][1], vn2 = vn_sm[el][2];
            atomicAdd(op,        fmaf(wvv, vp[tid      ], vn0 * wvs));
            atomicAdd(op + 128,  fmaf(wvv, vp[tid + 128], vn1 * wvs));
            atomicAdd(op + 256,  fmaf(wvv, vp[tid + 256], vn2 * wvs));
        }
    }
}

// ---------------------------------------------------------------------------
extern "C" void kernel_launch(void* const* d_in, const int* in_sizes, int n_in,
                              void* d_out, int out_size) {
    const float* s    = (const float*)d_in[0];
    const float* vec  = (const float*)d_in[1];
    const float* ev   = (const float*)d_in[2];
    const float* ed   = (const float*)d_in[3];
    const float* erbf = (const float*)d_in[4];
    const float* Ws1  = (const float*)d_in[5];
    const float* bs1  = (const float*)d_in[6];
    const float* Ws2  = (const float*)d_in[7];
    const float* bs2  = (const float*)d_in[8];
    const float* Wrbf = (const float*)d_in[9];
    const float* brbf = (const float*)d_in[10];
    const int*   eidx = (const int*)d_in[11];
    const int*   rcp  = (const int*)d_in[12];

    const int n_nodes = in_sizes[0] / F_DIM;
    const int n_edges = in_sizes[3];
    float* out_ds   = (float*)d_out;
    float* out_dvec = out_ds + (size_t)n_nodes * F_DIM;

    // 1) zero the (poisoned) output
    int zthreads = 256;
    int zblocks  = (out_size / 4 + zthreads - 1) / zthreads;
    zero_kernel<<<zblocks, zthreads>>>((float*)d_out, out_size);

    // 2) per-node MLP -> g_phi
    node_mlp_kernel<<<(n_nodes + TILE_M - 1) / TILE_M, 256>>>(
        s, Ws1, bs1, Ws2, bs2, n_nodes);

    // 3) per-edge filter + scatter
    int nb = (n_edges + EB - 1) / EB;
    edge_kernel<<<nb, 128>>>(vec, ev, ed, erbf, Wrbf, brbf, eidx,
                             out_ds, out_dvec, n_edges, rcp);
}

// round 2
// speedup vs baseline: 1.0303x; 1.0303x over previous
#include <cuda_runtime.h>
#include <cuda_bf16.h>
#include <math.h>

// ---------------------------------------------------------------------------
// MessageBlock:
//   phi_node = Linear2(silu(Linear1(s)))           (per-NODE, not per-edge!)
//   per edge e: W = (rbf @ Wrbf^T + brbf) * fcut(d)
//               msg = phi_node[src] * W  -> split ws/wvv/wvs
//               ds[dst]   += ws
//               dvec[dst] += wvv*vec[src] + (ev/d) outer wvs
// ---------------------------------------------------------------------------

#define F_DIM   128
#define PHI_DIM 384
#define RBF_D   20
#define TILE_M  32
#define KC      16
#define EB      64   // edges staged per batch

typedef unsigned long long ull;

// scratch for per-node phi (15.7 MB), static device allocation (allowed)
__device__ float g_phi[10240 * PHI_DIM];

__device__ __forceinline__ float decode_rc(const int* p) {
    int v = *p;
    if (v > 0 && v < 1000000) return (float)v;   // int32 scalar
    return __uint_as_float((unsigned)v);          // float32 scalar bits
}

// ---- packed f32x2 helpers (sm_103a FFMA2 path) -----------------------------
__device__ __forceinline__ ull pk2(float lo, float hi) {
    ull r; asm("mov.b64 %0, {%1, %2};" : "=l"(r) : "f"(lo), "f"(hi)); return r;
}
__device__ __forceinline__ ull fma2(ull a, ull b, ull c) {
    ull d; asm("fma.rn.f32x2 %0, %1, %2, %3;" : "=l"(d) : "l"(a), "l"(b), "l"(c));
    return d;
}
__device__ __forceinline__ float2 unpk2(ull p) {
    float2 v; asm("mov.b64 {%0, %1}, %2;" : "=f"(v.x), "=f"(v.y) : "l"(p));
    return v;
}

// ---------------------------------------------------------------------------
// zero-fill output
// ---------------------------------------------------------------------------
__global__ void zero_kernel(float* __restrict__ p, int n) {
    int i = (blockIdx.x * blockDim.x + threadIdx.x) * 4;
    if (i + 3 < n) {
        *(float4*)(p + i) = make_float4(0.f, 0.f, 0.f, 0.f);
    } else {
        for (int k = i; k < n; k++) p[k] = 0.f;
    }
}

// ---------------------------------------------------------------------------
// Node MLP: phi = (silu(s @ Ws1^T + bs1)) @ Ws2^T + bs2   -> g_phi [N,384]
// 256 threads, TILE_M=32 nodes, 4x4 register tile, packed f32x2 accumulators
// over the n-dimension.
// ---------------------------------------------------------------------------
__global__ void __launch_bounds__(256) node_mlp_kernel(
    const float* __restrict__ s,
    const float* __restrict__ Ws1, const float* __restrict__ bs1,
    const float* __restrict__ Ws2, const float* __restrict__ bs2,
    int n_nodes)
{
    __shared__ __align__(16) float s_sm[TILE_M][F_DIM];     // 16 KB
    __shared__ __align__(16) float h_sm[TILE_M][F_DIM];     // 16 KB
    __shared__ __align__(16) float w_sm[KC][F_DIM + 4];     // pad keeps 16B align

    const int tid   = threadIdx.x;
    const int m_blk = blockIdx.x * TILE_M;
    const int n_idx = tid & 31;       // 32 n-groups of 4  -> n in [0,128)
    const int m_idx = tid >> 5;       // 8  m-groups of 4  -> m in [0,32)
    const int n0 = n_idx * 4;
    const int m0 = m_idx * 4;

    // stage s tile (zero-pad past n_nodes)
    for (int i = tid; i < TILE_M * 32; i += 256) {
        int m = i >> 5;
        float4 v = make_float4(0.f, 0.f, 0.f, 0.f);
        if (m_blk + m < n_nodes)
            v = ((const float4*)s)[(size_t)(m_blk + m) * 32 + (i & 31)];
        ((float4*)s_sm)[i] = v;
    }

    ull accp[4][2];   // [m-sub][n-pair]  -> covers 4m x 4n in packed fp32 pairs

    // ---------------- stage 1: h = silu(s @ Ws1^T + bs1) ----------------
    #pragma unroll
    for (int i = 0; i < 4; i++) { accp[i][0] = 0ull; accp[i][1] = 0ull; }

    for (int kc = 0; kc < F_DIM; kc += KC) {
        __syncthreads();
        for (int i = tid; i < KC * F_DIM; i += 256) {
            int kk = i & (KC - 1);
            int n  = i >> 4;
            w_sm[kk][n] = Ws1[n * F_DIM + kc + kk];
        }
        __syncthreads();
        #pragma unroll
        for (int k4 = 0; k4 < KC; k4 += 4) {
            float a[4][4];
            #pragma unroll
            for (int i = 0; i < 4; i++) {
                float4 t = *(const float4*)&s_sm[m0 + i][kc + k4];
                a[i][0] = t.x; a[i][1] = t.y; a[i][2] = t.z; a[i][3] = t.w;
            }
            #pragma unroll
            for (int kk = 0; kk < 4; kk++) {
                double2 bq = *(const double2*)&w_sm[k4 + kk][n0];
                ull bA = __double_as_longlong(bq.x);
                ull bB = __double_as_longlong(bq.y);
                #pragma unroll
                for (int i = 0; i < 4; i++) {
                    ull aa = pk2(a[i][kk], a[i][kk]);
                    accp[i][0] = fma2(aa, bA, accp[i][0]);
                    accp[i][1] = fma2(aa, bB, accp[i][1]);
                }
            }
        }
    }
    // silu + bias -> h_sm
    {
        float bb[4];
        #pragma unroll
        for (int j = 0; j < 4; j++) bb[j] = bs1[n0 + j];
        #pragma unroll
        for (int i = 0; i < 4; i++) {
            float2 e0 = unpk2(accp[i][0]);
            float2 e1 = unpk2(accp[i][1]);
            float4 hv; float x;
            x = e0.x + bb[0]; hv.x = x / (1.f + __expf(-x));
            x = e0.y + bb[1]; hv.y = x / (1.f + __expf(-x));
            x = e1.x + bb[2]; hv.z = x / (1.f + __expf(-x));
            x = e1.y + bb[3]; hv.w = x / (1.f + __expf(-x));
            *(float4*)&h_sm[m0 + i][n0] = hv;
        }
    }

    // ---------------- stage 2: phi = h @ Ws2^T + bs2 (3 passes of 128) --
    for (int p = 0; p < 3; p++) {
        #pragma unroll
        for (int i = 0; i < 4; i++) { accp[i][0] = 0ull; accp[i][1] = 0ull; }

        const float* W2 = Ws2 + (size_t)p * 128 * F_DIM;
        for (int kc = 0; kc < F_DIM; kc += KC) {
            __syncthreads();   // also orders h_sm writes before first read
            for (int i = tid; i < KC * F_DIM; i += 256) {
                int kk = i & (KC - 1);
                int n  = i >> 4;
                w_sm[kk][n] = W2[n * F_DIM + kc + kk];
            }
            __syncthreads();
            #pragma unroll
            for (int k4 = 0; k4 < KC; k4 += 4) {
                float a[4][4];
                #pragma unroll
                for (int i = 0; i < 4; i++) {
                    float4 t = *(const float4*)&h_sm[m0 + i][kc + k4];
                    a[i][0] = t.x; a[i][1] = t.y; a[i][2] = t.z; a[i][3] = t.w;
                }
                #pragma unroll
                for (int kk = 0; kk < 4; kk++) {
                    double2 bq = *(const double2*)&w_sm[k4 + kk][n0];
                    ull bA = __double_as_longlong(bq.x);
                    ull bB = __double_as_longlong(bq.y);
                    #pragma unroll
                    for (int i = 0; i < 4; i++) {
                        ull aa = pk2(a[i][kk], a[i][kk]);
                        accp[i][0] = fma2(aa, bA, accp[i][0]);
                        accp[i][1] = fma2(aa, bB, accp[i][1]);
                    }
                }
            }
        }
        float bb[4];
        #pragma unroll
        for (int j = 0; j < 4; j++) bb[j] = bs2[p * 128 + n0 + j];
        #pragma unroll
        for (int i = 0; i < 4; i++) {
            if (m_blk + m0 + i < n_nodes) {
                float2 e0 = unpk2(accp[i][0]);
                float2 e1 = unpk2(accp[i][1]);
                float4 ov = make_float4(e0.x + bb[0], e0.y + bb[1],
                                        e1.x + bb[2], e1.y + bb[3]);
                *(float4*)&g_phi[(size_t)(m_blk + m0 + i) * PHI_DIM + p * 128 + n0] = ov;
            }
        }
    }
}

// ---------------------------------------------------------------------------
// Edge kernel: 128 threads, thread t owns feature channels {t, t+128, t+256}.
// Wrbf rows live as 10 packed f32x2 pairs per channel (60 regs). rbf values
// read as double2 (LDS.128 -> register pairs) and consumed by fma.rn.f32x2:
// 30 FMA2 + 5 LDS per edge per thread instead of 60 FFMA + 20 LDS.
// ---------------------------------------------------------------------------
__global__ void __launch_bounds__(128) edge_kernel(
    const float* __restrict__ vec,
    const float* __restrict__ edge_vector,
    const float* __restrict__ edge_distance,
    const float* __restrict__ edge_rbf,
    const float* __restrict__ Wrbf, const float* __restrict__ brbf,
    const int*   __restrict__ edge_idx,
    float* __restrict__ out_ds, float* __restrict__ out_dvec,
    int n_edges, const int* __restrict__ cutoff_ptr)
{
    __shared__ __align__(16) float rbf_sm[EB * RBF_D];   // 5 KB
    __shared__ float4 geo_sm[EB];                        // vn0,vn1,vn2,fcut
    __shared__ int2   idx_sm[EB];                        // (dst, src)

    const int tid = threadIdx.x;
    const float rc     = decode_rc(cutoff_ptr);
    const float inv_rc = 1.0f / rc;

    // packed weight pairs: wpX[q] = (W[ch][2q], W[ch][2q+1])
    ull wp0[RBF_D / 2], wp1[RBF_D / 2], wp2[RBF_D / 2];
    #pragma unroll
    for (int q = 0; q < RBF_D / 2; q++) {
        wp0[q] = pk2(Wrbf[(tid      ) * RBF_D + 2 * q], Wrbf[(tid      ) * RBF_D + 2 * q + 1]);
        wp1[q] = pk2(Wrbf[(tid + 128) * RBF_D + 2 * q], Wrbf[(tid + 128) * RBF_D + 2 * q + 1]);
        wp2[q] = pk2(Wrbf[(tid + 256) * RBF_D + 2 * q], Wrbf[(tid + 256) * RBF_D + 2 * q + 1]);
    }
    const float b0 = brbf[tid], b1 = brbf[tid + 128], b2 = brbf[tid + 256];

    const int n_batches = (n_edges + EB - 1) / EB;
    for (int batch = blockIdx.x; batch < n_batches; batch += gridDim.x) {
        const int e0  = batch * EB;
        const int cnt = min(EB, n_edges - e0);

        __syncthreads();  // protect smem reuse across batches
        // rbf: cnt*20 floats, always a multiple of 4; global base 16B-aligned
        {
            const float4* src4 = (const float4*)(edge_rbf + (size_t)e0 * RBF_D);
            float4* dst4 = (float4*)rbf_sm;
            const int n4 = cnt * (RBF_D / 4);
            for (int i = tid; i < n4; i += 128) dst4[i] = src4[i];
        }
        if (tid < cnt) {
            const int e = e0 + tid;
            const float d = edge_distance[e];
            float fc = 0.5f * (cospif(d * inv_rc) + 1.0f);
            fc = (d < rc) ? fc : 0.0f;
            const float inv_d = 1.0f / d;
            geo_sm[tid] = make_float4(edge_vector[e * 3 + 0] * inv_d,
                                      edge_vector[e * 3 + 1] * inv_d,
                                      edge_vector[e * 3 + 2] * inv_d,
                                      fc);
            idx_sm[tid] = make_int2(edge_idx[e],              // dst (receiver)
                                    edge_idx[n_edges + e]);   // src (sender)
        }
        __syncthreads();

        #pragma unroll 1
        for (int el = 0; el < cnt; el++) {
            const int2  ii = idx_sm[el];
            const float4 g = geo_sm[el];
            const int dst = ii.x, src = ii.y;

            // rbf dot: 5 x LDS.128 + 30 x fma.rn.f32x2
            const double2* fp = (const double2*)(rbf_sm + el * RBF_D);
            ull acc0 = 0ull, acc1 = 0ull, acc2 = 0ull;
            #pragma unroll
            for (int q = 0; q < 5; q++) {
                double2 f = fp[q];
                ull fA = __double_as_longlong(f.x);
                ull fB = __double_as_longlong(f.y);
                acc0 = fma2(fA, wp0[2 * q], acc0);
                acc1 = fma2(fA, wp1[2 * q], acc1);
                acc2 = fma2(fA, wp2[2 * q], acc2);
                acc0 = fma2(fB, wp0[2 * q + 1], acc0);
                acc1 = fma2(fB, wp1[2 * q + 1], acc1);
                acc2 = fma2(fB, wp2[2 * q + 1], acc2);
            }
            float2 u0 = unpk2(acc0), u1 = unpk2(acc1), u2 = unpk2(acc2);
            const float fc = g.w;
            const float a0 = (u0.x + u0.y + b0) * fc;
            const float a1 = (u1.x + u1.y + b1) * fc;
            const float a2 = (u2.x + u2.y + b2) * fc;

            const float* ph = g_phi + (size_t)src * PHI_DIM;
            const float ws  = __ldg(ph + tid)       * a0;
            const float wvv = __ldg(ph + tid + 128) * a1;
            const float wvs = __ldg(ph + tid + 256) * a2;

            atomicAdd(out_ds + (size_t)dst * F_DIM + tid, ws);

            const float* vp = vec + (size_t)src * PHI_DIM;
            float* op = out_dvec + (size_t)dst * PHI_DIM + tid;
            atomicAdd(op,       fmaf(wvv, __ldg(vp + tid      ), g.x * wvs));
            atomicAdd(op + 128, fmaf(wvv, __ldg(vp + tid + 128), g.y * wvs));
            atomicAdd(op + 256, fmaf(wvv, __ldg(vp + tid + 256), g.z * wvs));
        }
    }
}

// ---------------------------------------------------------------------------
extern "C" void kernel_launch(void* const* d_in, const int* in_sizes, int n_in,
                              void* d_out, int out_size) {
    const float* s    = (const float*)d_in[0];
    const float* vec  = (const float*)d_in[1];
    const float* ev   = (const float*)d_in[2];
    const float* ed   = (const float*)d_in[3];
    const float* erbf = (const float*)d_in[4];
    const float* Ws1  = (const float*)d_in[5];
    const float* bs1  = (const float*)d_in[6];
    const float* Ws2  = (const float*)d_in[7];
    const float* bs2  = (const float*)d_in[8];
    const float* Wrbf = (const float*)d_in[9];
    const float* brbf = (const float*)d_in[10];
    const int*   eidx = (const int*)d_in[11];
    const int*   rcp  = (const int*)d_in[12];

    const int n_nodes = in_sizes[0] / F_DIM;
    const int n_edges = in_sizes[3];
    float* out_ds   = (float*)d_out;
    float* out_dvec = out_ds + (size_t)n_nodes * F_DIM;

    // 1) zero the (poisoned) output
    int zthreads = 256;
    int zblocks  = (out_size / 4 + zthreads - 1) / zthreads;
    zero_kernel<<<zblocks, zthreads>>>((float*)d_out, out_size);

    // 2) per-node MLP -> g_phi
    node_mlp_kernel<<<(n_nodes + TILE_M - 1) / TILE_M, 256>>>(
        s, Ws1, bs1, Ws2, bs2, n_nodes);

    // 3) per-edge filter + scatter
    int nb = (n_edges + EB - 1) / EB;
    edge_kernel<<<nb, 128>>>(vec, ev, ed, erbf, Wrbf, brbf, eidx,
                             out_ds, out_dvec, n_edges, rcp);
}